// round 8
// baseline (speedup 1.0000x reference)
#include <cuda_runtime.h>
#include <cuda_bf16.h>
#include <math.h>

// ---------------------------------------------------------------------------
// Problem constants
// ---------------------------------------------------------------------------
#define NLEV 16
#define TSZ  (1 << 19)
#define TMASK (TSZ - 1)
#define HASH_PRIME 2654435761u

typedef unsigned long long u64;

// Weight blob: wp1[12*64] | wp2[64*64] | wp3[64] | wt[32*68] | bt[68]
#define OFF_WP1 0
#define OFF_WP2 768
#define OFF_WP3 4864
#define OFF_WT  4928
#define OFF_BT  7104
#define TOTW    7172

__device__   float g_wb[TOTW];     // staging (prep kernel output)
__constant__ float c_wb[TOTW];     // uniform access via const port (LDC)

struct LevelP {
    float scale[NLEV];
    int   res[NLEV];
    int   dense[NLEV];
};

// Shared layout (floats): NO weights in smem anymore.
#define ACT_STRIDE 132
#define SM_ACT   0                         // 65 x 132 = 8580 (encT rows0-11 / h1T rows0-63 / out-stage 128x65; row 64 = prefetch slack)
#define SM_FEAT  8580                      // 33 x 132 = 4356 (row 32 = slack)
#define SM_Z     (SM_FEAT + 4356)          // 128
#define SM_X64   (SM_Z + 128)              // 128
#define SM_PZ    (SM_X64 + 128)            // 128
#define SMEM_FLOATS (SM_PZ + 128)
#define SMEM_BYTES  (SMEM_FLOATS * 4)

// ---------------------------------------------------------------------------
// f32x2 helpers
// ---------------------------------------------------------------------------
__device__ __forceinline__ u64 dup2(float a) {
    u64 r; asm("mov.b64 %0, {%1, %1};" : "=l"(r) : "f"(a)); return r;
}
__device__ __forceinline__ u64 pack2(float a, float b) {
    u64 r; asm("mov.b64 %0, {%1, %2};" : "=l"(r) : "f"(a), "f"(b)); return r;
}
__device__ __forceinline__ void unpack2(u64 v, float &a, float &b) {
    asm("mov.b64 {%0, %1}, %2;" : "=f"(a), "=f"(b) : "l"(v));
}
__device__ __forceinline__ void fma2(u64 &d, u64 a, u64 b) {
    asm("fma.rn.f32x2 %0, %1, %2, %0;" : "+l"(d) : "l"(a), "l"(b));
}
__device__ __forceinline__ float sigm(float x) {
    return __fdividef(1.0f, 1.0f + __expf(-x));
}

// ---------------------------------------------------------------------------
// 8pt x 4col register-tiled GEMM: A from SMEM (prefetched), B from CONSTANT.
//   pg = tid>>4 (2 per warp), cg = tid&15 (16 per warp)
//   acc[p2*4+c] packs points (pg*8+2p2, +1) for col cg*4+c.
// A prefetch reads one row past K (slack row, value discarded).
// ---------------------------------------------------------------------------
template <int K, int NC, int UNR>
__device__ __forceinline__ void gemm84(u64* __restrict__ acc,
                                       const float* __restrict__ aT,
                                       int boff, int pg, int cg) {
    const int bcol = boff + cg * 4;
    const float* arow = aT + pg * 8;
    ulonglong2 A0 = *reinterpret_cast<const ulonglong2*>(arow);
    ulonglong2 A1 = *reinterpret_cast<const ulonglong2*>(arow + 4);
    #pragma unroll UNR
    for (int k = 0; k < K; k++) {
        const float* an = arow + (k + 1) * ACT_STRIDE;
        ulonglong2 nA0 = *reinterpret_cast<const ulonglong2*>(an);
        ulonglong2 nA1 = *reinterpret_cast<const ulonglong2*>(an + 4);
        float4 b4 = *reinterpret_cast<const float4*>(&c_wb[bcol + k * NC]);  // LDC.128
        u64 b0 = dup2(b4.x), b1 = dup2(b4.y), b2 = dup2(b4.z), b3 = dup2(b4.w);
        u64 a[4] = {A0.x, A0.y, A1.x, A1.y};
        #pragma unroll
        for (int p = 0; p < 4; p++) {
            fma2(acc[p * 4 + 0], a[p], b0);
            fma2(acc[p * 4 + 1], a[p], b1);
            fma2(acc[p * 4 + 2], a[p], b2);
            fma2(acc[p * 4 + 3], a[p], b3);
        }
        A0 = nA0; A1 = nA1;
    }
}

// ---------------------------------------------------------------------------
// Prep kernel: pack weights into padded blob (then D2D copy -> c_wb)
// ---------------------------------------------------------------------------
__global__ void prep_weights(const float* __restrict__ W_tiny,
                             const float* __restrict__ b_tiny,
                             const float* __restrict__ Wp1,
                             const float* __restrict__ Wp2,
                             const float* __restrict__ Wp3) {
    int t = threadIdx.x;
    for (int i = t; i < 12 * 64; i += blockDim.x) g_wb[OFF_WP1 + i] = Wp1[i];
    for (int i = t; i < 64 * 64; i += blockDim.x) g_wb[OFF_WP2 + i] = Wp2[i];
    if (t < 64) g_wb[OFF_WP3 + t] = Wp3[t];
    for (int i = t; i < 32 * 68; i += blockDim.x) {
        int k = i / 68, j = i % 68;
        g_wb[OFF_WT + i] = (j < 65) ? W_tiny[k * 65 + j] : 0.0f;
    }
    if (t < 68) g_wb[OFF_BT + t] = (t < 65) ? b_tiny[t] : 0.0f;
}

// ---------------------------------------------------------------------------
// Fused kernel (897-µs structure + const-port B + shuffle prior + 3 blocks/SM)
// ---------------------------------------------------------------------------
__global__ void __launch_bounds__(256, 3)
sdf_kernel(const float* __restrict__ inputs,
           const float* __restrict__ tables,
           float* __restrict__ out,
           int N, LevelP P) {
    extern __shared__ float smem[];
    float* actT  = smem + SM_ACT;     // encT / h1T / out-stage
    float* featT = smem + SM_FEAT;
    float* sZ    = smem + SM_Z;
    float* sX64  = smem + SM_X64;
    float* sPZ   = smem + SM_PZ;

    const int tid  = threadIdx.x;
    const int pg   = tid >> 4;        // 0..15 (2 per warp)
    const int cg   = tid & 15;        // 0..15
    const int base = blockIdx.x * 128;
    const int cnt  = min(128, N - base);

    // =======================================================================
    // Split scalar phase: threads 0-127 encode; threads 128-255 hash-gather
    // =======================================================================
    if (tid < 128) {
        float x = 0.f, y = 0.f, z = 0.f;
        if (tid < cnt) {
            const float* ip = inputs + (size_t)(base + tid) * 3;
            x = ip[0]; y = ip[1]; z = ip[2];
        }
        const float PIF = 3.14159265358979323846f;
        float s, c, e[12];
        sincosf(x * PIF,          &s, &c); e[0] = s; e[3]  = c;
        sincosf(x * (2.0f * PIF), &s, &c); e[1] = s; e[4]  = c;
        sincosf(x * (4.0f * PIF), &s, &c); e[2] = s; e[5]  = c;
        sincosf(y * PIF,          &s, &c); e[6] = s; e[9]  = c;
        sincosf(y * (2.0f * PIF), &s, &c); e[7] = s; e[10] = c;
        sincosf(y * (4.0f * PIF), &s, &c); e[8] = s; e[11] = c;
        #pragma unroll
        for (int i = 0; i < 12; i++) actT[i * ACT_STRIDE + tid] = (tid < cnt) ? e[i] : 0.0f;
        sZ[tid] = z;
    } else {
        const int p = tid - 128;
        float x = 0.f, y = 0.f;
        if (p < cnt) {
            const float* ip = inputs + (size_t)(base + p) * 3;
            x = ip[0]; y = ip[1];
        }
        float feat[32];
        float x64 = 0.0f;
        if (p < cnt) {
            const float u = __fadd_rn(__fdiv_rn(x, 30.0f), 0.5f);
            const float v = __fadd_rn(__fdiv_rn(y, 30.0f), 0.5f);
            const float2* tb = reinterpret_cast<const float2*>(tables);
            #pragma unroll
            for (int l = 0; l < NLEV; l++) {
                float s  = P.scale[l];
                float px = __fadd_rn(__fmul_rn(u, s), 0.5f);
                float py = __fadd_rn(__fmul_rn(v, s), 0.5f);
                float fx = floorf(px), fy = floorf(py);
                float wx = px - fx,    wy = py - fy;
                int ix = (int)fx, iy = (int)fy;
                int i00, i10, i01, i11;
                if (P.dense[l]) {
                    int r = P.res[l];
                    i00 = ix + iy * r;  i10 = i00 + 1;
                    i01 = i00 + r;      i11 = i01 + 1;
                    i00 = min(max(i00, 0), TSZ - 1);
                    i10 = min(max(i10, 0), TSZ - 1);
                    i01 = min(max(i01, 0), TSZ - 1);
                    i11 = min(max(i11, 0), TSZ - 1);
                } else {
                    unsigned ux = (unsigned)ix, uy = (unsigned)iy;
                    unsigned hy0 = uy * HASH_PRIME;
                    unsigned hy1 = (uy + 1u) * HASH_PRIME;
                    i00 = (int)((ux        ^ hy0) & TMASK);
                    i10 = (int)(((ux + 1u) ^ hy0) & TMASK);
                    i01 = (int)((ux        ^ hy1) & TMASK);
                    i11 = (int)(((ux + 1u) ^ hy1) & TMASK);
                }
                const float2* t = tb + (size_t)l * TSZ;
                float2 f00 = __ldg(t + i00);
                float2 f10 = __ldg(t + i10);
                float2 f01 = __ldg(t + i01);
                float2 f11 = __ldg(t + i11);
                float omx = 1.0f - wx, omy = 1.0f - wy;
                feat[2 * l]     = (f00.x * omx + f10.x * wx) * omy + (f01.x * omx + f11.x * wx) * wy;
                feat[2 * l + 1] = (f00.y * omx + f10.y * wx) * omy + (f01.y * omx + f11.y * wx) * wy;
            }
        } else {
            #pragma unroll
            for (int k = 0; k < 32; k++) feat[k] = 0.0f;
        }
        #pragma unroll
        for (int k = 0; k < 32; k++) {
            featT[k * ACT_STRIDE + p] = feat[k];
            x64 += feat[k] * c_wb[OFF_WT + k * 68 + 64];      // LDC (uniform)
        }
        sX64[p] = x64 + c_wb[OFF_BT + 64];
    }
    __syncthreads();

    u64 acc[16];

    // ---- GEMM1: h1 = sigmoid(enc @ Wp1) ----
    #pragma unroll
    for (int q = 0; q < 16; q++) acc[q] = 0ull;
    gemm84<12, 64, 12>(acc, actT, OFF_WP1, pg, cg);
    __syncthreads();                  // encT reads done; actT rows become h1T
    #pragma unroll
    for (int c = 0; c < 4; c++) {
        float* rw = actT + (cg * 4 + c) * ACT_STRIDE + pg * 8;
        #pragma unroll
        for (int p2 = 0; p2 < 4; p2++) {
            float a, b; unpack2(acc[p2 * 4 + c], a, b);
            *reinterpret_cast<u64*>(rw + 2 * p2) = pack2(sigm(a), sigm(b));
        }
    }
    __syncthreads();

    // ---- GEMM2: h2 = sigmoid(h1 @ Wp2); prior via half-warp shuffle ----
    #pragma unroll
    for (int q = 0; q < 16; q++) acc[q] = 0ull;
    gemm84<64, 64, 8>(acc, actT, OFF_WP2, pg, cg);
    {
        float pp[8];
        #pragma unroll
        for (int p2 = 0; p2 < 4; p2++) { pp[2 * p2] = 0.f; pp[2 * p2 + 1] = 0.f; }
        #pragma unroll
        for (int c = 0; c < 4; c++) {
            const float w3 = c_wb[OFF_WP3 + cg * 4 + c];      // LDC
            #pragma unroll
            for (int p2 = 0; p2 < 4; p2++) {
                float a, b; unpack2(acc[p2 * 4 + c], a, b);
                pp[2 * p2]     += sigm(a) * w3;
                pp[2 * p2 + 1] += sigm(b) * w3;
            }
        }
        // reduce over the 16 cg-lanes of this half-warp (pg fixed per half-warp)
        #pragma unroll
        for (int m = 1; m < 16; m <<= 1) {
            #pragma unroll
            for (int i = 0; i < 8; i++)
                pp[i] += __shfl_xor_sync(0xFFFFFFFFu, pp[i], m);
        }
        if (cg == 0) {
            const float bt0 = c_wb[OFF_BT];
            #pragma unroll
            for (int i = 0; i < 8; i++) {
                const int pt = pg * 8 + i;
                sPZ[pt] = (sZ[pt] - bt0) - pp[i];             // z - bt0 - prior
            }
        }
    }

    // ---- GEMM3: feat @ wt[:,0:64] ----
    #pragma unroll
    for (int q = 0; q < 16; q++) acc[q] = 0ull;
    gemm84<32, 68, 8>(acc, featT, OFF_WT, pg, cg);
    __syncthreads();                  // h1T reads done (actT -> out-stage); sPZ visible

    // ---- assembly into out-stage (actT region) ----
    {
        float* ost = actT;
        #pragma unroll
        for (int c = 0; c < 4; c++) {
            const int col = cg * 4 + c;
            const float bias = c_wb[OFF_BT + col];            // LDC
            #pragma unroll
            for (int p2 = 0; p2 < 4; p2++) {
                float a, b; unpack2(acc[p2 * 4 + c], a, b);
                const int pt = pg * 8 + 2 * p2;
                if (col == 0) {
                    ost[pt * 65]       = sPZ[pt] - a;
                    ost[(pt + 1) * 65] = sPZ[pt + 1] - b;
                } else {
                    ost[pt * 65 + col]       = a + bias;
                    ost[(pt + 1) * 65 + col] = b + bias;
                }
            }
        }
        if (tid < 128) ost[tid * 65 + 64] = sX64[tid];
    }
    __syncthreads();

    // ---- coalesced flush ----
    if (cnt == 128) {
        float4* o4 = reinterpret_cast<float4*>(out + (size_t)base * 65);
        const float4* s4 = reinterpret_cast<const float4*>(actT);
        #pragma unroll
        for (int t = tid; t < (128 * 65) / 4; t += 256) o4[t] = s4[t];
    } else if (cnt > 0) {
        const int tot = cnt * 65;
        for (int t = tid; t < tot; t += 256) out[(size_t)base * 65 + t] = actT[t];
    }
}

// ---------------------------------------------------------------------------
// Launch
// ---------------------------------------------------------------------------
extern "C" void kernel_launch(void* const* d_in, const int* in_sizes, int n_in,
                              void* d_out, int out_size) {
    const float* inputs  = (const float*)d_in[0];
    const float* tables  = (const float*)d_in[1];
    const float* W_tiny  = (const float*)d_in[2];
    const float* b_tiny  = (const float*)d_in[3];
    const float* Wp1     = (const float*)d_in[4];
    const float* Wp2     = (const float*)d_in[5];
    const float* Wp3     = (const float*)d_in[6];
    float* out           = (float*)d_out;

    const int N = in_sizes[0] / 3;

    LevelP P;
    for (int l = 0; l < NLEV; l++) {
        double sc = pow(2.0, (double)l * log2(1.5)) * 16.0 - 1.0;
        int res = (int)ceil(sc) + 1;
        P.scale[l] = (float)sc;
        P.res[l]   = res;
        P.dense[l] = ((long long)res * (long long)res <= (long long)TSZ) ? 1 : 0;
    }

    static int attr_done = 0;
    if (!attr_done) {
        cudaFuncSetAttribute(sdf_kernel,
                             cudaFuncAttributeMaxDynamicSharedMemorySize, SMEM_BYTES);
        attr_done = 1;
    }

    // stage weights, then copy into the constant bank (all graph-capturable)
    prep_weights<<<1, 256>>>(W_tiny, b_tiny, Wp1, Wp2, Wp3);
    void *cwa = nullptr, *gwa = nullptr;
    cudaGetSymbolAddress(&cwa, c_wb);
    cudaGetSymbolAddress(&gwa, g_wb);
    cudaMemcpyAsync(cwa, gwa, TOTW * sizeof(float), cudaMemcpyDeviceToDevice, 0);

    const int tiles = (N + 127) / 128;
    sdf_kernel<<<tiles, 256, SMEM_BYTES>>>(inputs, tables, out, N, P);
}

// round 9
// speedup vs baseline: 2.8913x; 2.8913x over previous
#include <cuda_runtime.h>
#include <cuda_bf16.h>
#include <math.h>

// ---------------------------------------------------------------------------
// Problem constants
// ---------------------------------------------------------------------------
#define NLEV 16
#define TSZ  (1 << 19)
#define TMASK (TSZ - 1)
#define HASH_PRIME 2654435761u

typedef unsigned long long u64;

// Weight blob: wp1[12*64] | wp2[64*64] | wp3[64] | wt[32*68] | bt[68]
#define OFF_WP1 0
#define OFF_WP2 768
#define OFF_WP3 4864
#define OFF_WT  4928
#define OFF_BT  7104
#define TOTW    7172

struct __align__(16) Weights {
    float wp1[12 * 64];
    float wp2[64 * 64];
    float wp3[64];
    float wt [32 * 68];
    float bt [68];
};
__device__ Weights g_w;

struct LevelP {
    float scale[NLEV];
    int   res[NLEV];
    int   dense[NLEV];
};

// Shared layout (floats); all regions 16B aligned, stride 128 (swizzle handles banks)
#define SM_ENC   TOTW               // 13 x 128 = 1664 (row 12 = prefetch slack)
#define SM_FEAT  (SM_ENC + 1664)    // 33 x 128 = 4224 (row 32 = slack; sPar reuse)
#define SM_H1    (SM_FEAT + 4224)   // 65 x 128 = 8320 (row 64 = slack; out-stage 128x65)
#define SM_Z     (SM_H1 + 8320)     // 128
#define SM_X64   (SM_Z + 128)       // 128
#define SM_PZ    (SM_X64 + 128)     // 128
#define SMEM_FLOATS (SM_PZ + 128)
#define SMEM_BYTES  (SMEM_FLOATS * 4)

// ---------------------------------------------------------------------------
// f32x2 helpers
// ---------------------------------------------------------------------------
__device__ __forceinline__ u64 dup2(float a) {
    u64 r; asm("mov.b64 %0, {%1, %1};" : "=l"(r) : "f"(a)); return r;
}
__device__ __forceinline__ u64 pack2(float a, float b) {
    u64 r; asm("mov.b64 %0, {%1, %2};" : "=l"(r) : "f"(a), "f"(b)); return r;
}
__device__ __forceinline__ void unpack2(u64 v, float &a, float &b) {
    asm("mov.b64 {%0, %1}, %2;" : "=f"(a), "=f"(b) : "l"(v));
}
__device__ __forceinline__ void fma2(u64 &d, u64 a, u64 b) {
    asm("fma.rn.f32x2 %0, %1, %2, %0;" : "+l"(d) : "l"(a), "l"(b));
}
__device__ __forceinline__ float sigm(float x) {
    return __fdividef(1.0f, 1.0f + __expf(-x));
}

// ---------------------------------------------------------------------------
// 8pt x 4col register-tiled GEMM, warp covers 32pts x 32cols:
//   pg = (w>>1)*4 + (lane>>3)   (4 distinct pg/warp -> A LDS.128: 1 wf)
//   cg = (w&1)*8 + (lane&7)     (8 distinct cg/warp -> B LDS.128: 1 wf)
// acc[p2*4+c] packs points (pg*8+2p2, +1) for col cg*4+c.
// SWZ: A row k stored with point-block swizzle pg ^ ((k>>2)&3).
// A prefetch reads one row past K (slack row, value discarded).
// ---------------------------------------------------------------------------
template <int K, int NC, int SWZ, int UNR>
__device__ __forceinline__ void gemm84(u64* __restrict__ acc,
                                       const float* __restrict__ aT,
                                       const float* __restrict__ B,
                                       int pg, int cg) {
    const float* bp = B + cg * 4;
    #define A_PTR(kk) (aT + (kk) * 128 + ((SWZ ? (pg ^ (((kk) >> 2) & 3)) : pg) << 3))
    const float* a0 = A_PTR(0);
    ulonglong2 A0 = *reinterpret_cast<const ulonglong2*>(a0);
    ulonglong2 A1 = *reinterpret_cast<const ulonglong2*>(a0 + 4);
    #pragma unroll UNR
    for (int k = 0; k < K; k++) {
        const float* an = A_PTR(k + 1);
        ulonglong2 nA0 = *reinterpret_cast<const ulonglong2*>(an);
        ulonglong2 nA1 = *reinterpret_cast<const ulonglong2*>(an + 4);
        float4 b4 = *reinterpret_cast<const float4*>(bp + k * NC);
        u64 b0 = dup2(b4.x), b1 = dup2(b4.y), b2 = dup2(b4.z), b3 = dup2(b4.w);
        u64 a[4] = {A0.x, A0.y, A1.x, A1.y};
        #pragma unroll
        for (int p = 0; p < 4; p++) {
            fma2(acc[p * 4 + 0], a[p], b0);
            fma2(acc[p * 4 + 1], a[p], b1);
            fma2(acc[p * 4 + 2], a[p], b2);
            fma2(acc[p * 4 + 3], a[p], b3);
        }
        A0 = nA0; A1 = nA1;
    }
    #undef A_PTR
}

// ---------------------------------------------------------------------------
// Prep kernel
// ---------------------------------------------------------------------------
__global__ void prep_weights(const float* __restrict__ W_tiny,
                             const float* __restrict__ b_tiny,
                             const float* __restrict__ Wp1,
                             const float* __restrict__ Wp2,
                             const float* __restrict__ Wp3) {
    int t = threadIdx.x;
    for (int i = t; i < 12 * 64; i += blockDim.x) g_w.wp1[i] = Wp1[i];
    for (int i = t; i < 64 * 64; i += blockDim.x) g_w.wp2[i] = Wp2[i];
    if (t < 64) g_w.wp3[t] = Wp3[t];
    for (int i = t; i < 32 * 68; i += blockDim.x) {
        int k = i / 68, j = i % 68;
        g_w.wt[i] = (j < 65) ? W_tiny[k * 65 + j] : 0.0f;
    }
    if (t < 68) g_w.bt[t] = (t < 65) ? b_tiny[t] : 0.0f;
}

// ---------------------------------------------------------------------------
// Fused kernel: 897-µs structure (split scalar phase, smem weights) with
// remapped warps + swizzled h1T.
// ---------------------------------------------------------------------------
__global__ void __launch_bounds__(256, 2)
sdf_kernel(const float* __restrict__ inputs,
           const float* __restrict__ tables,
           float* __restrict__ out,
           int N, LevelP P) {
    extern __shared__ float smem[];
    float* sw    = smem;
    float* encT  = smem + SM_ENC;
    float* featT = smem + SM_FEAT;
    float* h1T   = smem + SM_H1;     // also out-stage
    float* sZ    = smem + SM_Z;
    float* sX64  = smem + SM_X64;
    float* sPZ   = smem + SM_PZ;

    const int tid  = threadIdx.x;
    const int lane = tid & 31;
    const int w    = tid >> 5;
    const int pg   = ((w >> 1) << 2) + (lane >> 3);   // 0..15
    const int cg   = ((w & 1) << 3) + (lane & 7);     // 0..15
    const int cgl  = lane & 7;
    const int base = blockIdx.x * 128;
    const int cnt  = min(128, N - base);

    // ---- cooperative weight load ----
    {
        const float4* src = reinterpret_cast<const float4*>(g_w.wp1);
        float4* dst = reinterpret_cast<float4*>(sw);
        #pragma unroll
        for (int i = tid; i < TOTW / 4; i += 256) dst[i] = src[i];
    }
    __syncthreads();

    // =======================================================================
    // Split scalar phase: threads 0-127 encode; threads 128-255 hash-gather
    // (identical to the 897-us kernel)
    // =======================================================================
    if (tid < 128) {
        float x = 0.f, y = 0.f, z = 0.f;
        if (tid < cnt) {
            const float* ip = inputs + (size_t)(base + tid) * 3;
            x = ip[0]; y = ip[1]; z = ip[2];
        }
        const float PIF = 3.14159265358979323846f;
        float s, c, e[12];
        sincosf(x * PIF,          &s, &c); e[0] = s; e[3]  = c;
        sincosf(x * (2.0f * PIF), &s, &c); e[1] = s; e[4]  = c;
        sincosf(x * (4.0f * PIF), &s, &c); e[2] = s; e[5]  = c;
        sincosf(y * PIF,          &s, &c); e[6] = s; e[9]  = c;
        sincosf(y * (2.0f * PIF), &s, &c); e[7] = s; e[10] = c;
        sincosf(y * (4.0f * PIF), &s, &c); e[8] = s; e[11] = c;
        #pragma unroll
        for (int i = 0; i < 12; i++) encT[i * 128 + tid] = (tid < cnt) ? e[i] : 0.0f;
        sZ[tid] = z;
    } else {
        const int p = tid - 128;
        float x = 0.f, y = 0.f;
        if (p < cnt) {
            const float* ip = inputs + (size_t)(base + p) * 3;
            x = ip[0]; y = ip[1];
        }
        float feat[32];
        float x64 = 0.0f;
        if (p < cnt) {
            const float u = __fadd_rn(__fdiv_rn(x, 30.0f), 0.5f);
            const float v = __fadd_rn(__fdiv_rn(y, 30.0f), 0.5f);
            const float2* tb = reinterpret_cast<const float2*>(tables);
            #pragma unroll
            for (int l = 0; l < NLEV; l++) {
                float s  = P.scale[l];
                float px = __fadd_rn(__fmul_rn(u, s), 0.5f);
                float py = __fadd_rn(__fmul_rn(v, s), 0.5f);
                float fx = floorf(px), fy = floorf(py);
                float wx = px - fx,    wy = py - fy;
                int ix = (int)fx, iy = (int)fy;
                int i00, i10, i01, i11;
                if (P.dense[l]) {
                    int r = P.res[l];
                    i00 = ix + iy * r;  i10 = i00 + 1;
                    i01 = i00 + r;      i11 = i01 + 1;
                    i00 = min(max(i00, 0), TSZ - 1);
                    i10 = min(max(i10, 0), TSZ - 1);
                    i01 = min(max(i01, 0), TSZ - 1);
                    i11 = min(max(i11, 0), TSZ - 1);
                } else {
                    unsigned ux = (unsigned)ix, uy = (unsigned)iy;
                    unsigned hy0 = uy * HASH_PRIME;
                    unsigned hy1 = (uy + 1u) * HASH_PRIME;
                    i00 = (int)((ux        ^ hy0) & TMASK);
                    i10 = (int)(((ux + 1u) ^ hy0) & TMASK);
                    i01 = (int)((ux        ^ hy1) & TMASK);
                    i11 = (int)(((ux + 1u) ^ hy1) & TMASK);
                }
                const float2* t = tb + (size_t)l * TSZ;
                float2 f00 = __ldg(t + i00);
                float2 f10 = __ldg(t + i10);
                float2 f01 = __ldg(t + i01);
                float2 f11 = __ldg(t + i11);
                float omx = 1.0f - wx, omy = 1.0f - wy;
                feat[2 * l]     = (f00.x * omx + f10.x * wx) * omy + (f01.x * omx + f11.x * wx) * wy;
                feat[2 * l + 1] = (f00.y * omx + f10.y * wx) * omy + (f01.y * omx + f11.y * wx) * wy;
            }
        } else {
            #pragma unroll
            for (int k = 0; k < 32; k++) feat[k] = 0.0f;
        }
        #pragma unroll
        for (int k = 0; k < 32; k++) {
            featT[k * 128 + p] = feat[k];
            x64 += feat[k] * sw[OFF_WT + k * 68 + 64];
        }
        sX64[p] = x64 + sw[OFF_BT + 64];
    }
    __syncthreads();

    u64 acc[16];

    // ---- GEMM1: h1 = sigmoid(enc @ Wp1) ----
    #pragma unroll
    for (int q = 0; q < 16; q++) acc[q] = 0ull;
    gemm84<12, 64, 0, 12>(acc, encT, sw + OFF_WP1, pg, cg);
    // swizzled + rotated transposed store to h1T (disjoint region, no pre-sync)
    #pragma unroll
    for (int c = 0; c < 4; c++) {
        const int col = cg * 4 + c;
        float* rw = h1T + col * 128 + ((pg ^ ((col >> 2) & 3)) << 3);
        #pragma unroll
        for (int q = 0; q < 4; q++) {
            const int p2 = (q + cgl) & 3;
            float a, b; unpack2(acc[p2 * 4 + c], a, b);
            *reinterpret_cast<u64*>(rw + 2 * p2) = pack2(sigm(a), sigm(b));
        }
    }
    __syncthreads();

    // ---- GEMM2: h2 = sigmoid(h1 @ Wp2); prior partials in regs ----
    #pragma unroll
    for (int q = 0; q < 16; q++) acc[q] = 0ull;
    gemm84<64, 64, 1, 8>(acc, h1T, sw + OFF_WP2, pg, cg);
    float ppa[4], ppb[4];
    #pragma unroll
    for (int p2 = 0; p2 < 4; p2++) { ppa[p2] = 0.f; ppb[p2] = 0.f; }
    #pragma unroll
    for (int c = 0; c < 4; c++) {
        const float w3 = sw[OFF_WP3 + cg * 4 + c];
        #pragma unroll
        for (int p2 = 0; p2 < 4; p2++) {
            float a, b; unpack2(acc[p2 * 4 + c], a, b);
            ppa[p2] += sigm(a) * w3;
            ppb[p2] += sigm(b) * w3;
        }
    }

    // ---- GEMM3: feat @ wt[:,0:64] ----
    #pragma unroll
    for (int q = 0; q < 16; q++) acc[q] = 0ull;
    gemm84<32, 68, 0, 8>(acc, featT, sw + OFF_WT, pg, cg);
    __syncthreads();   // featT reads done -> reuse as sPar

    // prior partial store (stride 136, rotated p2)
    {
        float* sPar = featT;
        #pragma unroll
        for (int q = 0; q < 4; q++) {
            const int p2 = (q + cgl) & 3;
            *reinterpret_cast<u64*>(sPar + cg * 136 + pg * 8 + 2 * p2) =
                pack2(ppa[p2], ppb[p2]);
        }
    }
    __syncthreads();

    // prior reduction + fold z/bias (threads 0-127)
    if (tid < 128) {
        const float* sPar = featT;
        float pr = 0.0f;
        #pragma unroll
        for (int c = 0; c < 16; c++) pr += sPar[c * 136 + tid];
        sPZ[tid] = (sZ[tid] - sw[OFF_BT]) - pr;   // z - bt0 - prior
    }
    __syncthreads();

    // ---- assembly into out-stage (h1T region), rotated p2 ----
    {
        float* ost = h1T;
        #pragma unroll
        for (int c = 0; c < 4; c++) {
            const int col = cg * 4 + c;
            const float bias = sw[OFF_BT + col];
            #pragma unroll
            for (int q = 0; q < 4; q++) {
                const int p2 = (q + cgl) & 3;
                float a, b; unpack2(acc[p2 * 4 + c], a, b);
                const int pt = pg * 8 + 2 * p2;
                if (col == 0) {
                    ost[pt * 65]       = sPZ[pt] - a;
                    ost[(pt + 1) * 65] = sPZ[pt + 1] - b;
                } else {
                    ost[pt * 65 + col]       = a + bias;
                    ost[(pt + 1) * 65 + col] = b + bias;
                }
            }
        }
        if (tid < 128) ost[tid * 65 + 64] = sX64[tid];
    }
    __syncthreads();

    // ---- coalesced flush ----
    if (cnt == 128) {
        float4* o4 = reinterpret_cast<float4*>(out + (size_t)base * 65);
        const float4* s4 = reinterpret_cast<const float4*>(h1T);
        #pragma unroll
        for (int t = tid; t < (128 * 65) / 4; t += 256) o4[t] = s4[t];
    } else if (cnt > 0) {
        const int tot = cnt * 65;
        for (int t = tid; t < tot; t += 256) out[(size_t)base * 65 + t] = h1T[t];
    }
}

// ---------------------------------------------------------------------------
// Launch
// ---------------------------------------------------------------------------
extern "C" void kernel_launch(void* const* d_in, const int* in_sizes, int n_in,
                              void* d_out, int out_size) {
    const float* inputs  = (const float*)d_in[0];
    const float* tables  = (const float*)d_in[1];
    const float* W_tiny  = (const float*)d_in[2];
    const float* b_tiny  = (const float*)d_in[3];
    const float* Wp1     = (const float*)d_in[4];
    const float* Wp2     = (const float*)d_in[5];
    const float* Wp3     = (const float*)d_in[6];
    float* out           = (float*)d_out;

    const int N = in_sizes[0] / 3;

    LevelP P;
    for (int l = 0; l < NLEV; l++) {
        double sc = pow(2.0, (double)l * log2(1.5)) * 16.0 - 1.0;
        int res = (int)ceil(sc) + 1;
        P.scale[l] = (float)sc;
        P.res[l]   = res;
        P.dense[l] = ((long long)res * (long long)res <= (long long)TSZ) ? 1 : 0;
    }

    static int attr_done = 0;
    if (!attr_done) {
        cudaFuncSetAttribute(sdf_kernel,
                             cudaFuncAttributeMaxDynamicSharedMemorySize, SMEM_BYTES);
        attr_done = 1;
    }

    prep_weights<<<1, 256>>>(W_tiny, b_tiny, Wp1, Wp2, Wp3);

    const int tiles = (N + 127) / 128;
    sdf_kernel<<<tiles, 256, SMEM_BYTES>>>(inputs, tables, out, N, P);
}

// round 10
// speedup vs baseline: 3.3573x; 1.1612x over previous
#include <cuda_runtime.h>
#include <cuda_bf16.h>
#include <math.h>

// ---------------------------------------------------------------------------
// Problem constants
// ---------------------------------------------------------------------------
#define NLEV 16
#define TSZ  (1 << 19)
#define TMASK (TSZ - 1)
#define HASH_PRIME 2654435761u

typedef unsigned long long u64;

// Weight blob: wp1[12*64] | wp2[64*64] | wp3[64] | wt[32*68] | bt[68]
#define OFF_WP1 0
#define OFF_WP2 768
#define OFF_WP3 4864
#define OFF_WT  4928
#define OFF_BT  7104
#define TOTW    7172

struct __align__(16) Weights {
    float wp1[12 * 64];
    float wp2[64 * 64];
    float wp3[64];
    float wt [32 * 68];
    float bt [68];
};
__device__ Weights g_w;

struct LevelP {
    float scale[NLEV];
    int   res[NLEV];
    int   dense[NLEV];
};

// Shared layout (floats), stride 132 as in the 897-us kernel
#define ACT_STRIDE 132
#define ACT_FLOATS  (64 * ACT_STRIDE)     // 8448: encT rows0-11 / h1T rows0-63 / out-stage 128x65
#define FEAT_FLOATS (33 * ACT_STRIDE)     // 4356 (row 32 = prefetch slack)
#define SM_FEAT  (TOTW + ACT_FLOATS)
#define SM_Z     (SM_FEAT + FEAT_FLOATS)  // 128
#define SM_X64   (SM_Z + 128)             // 128
#define SM_PZ    (SM_X64 + 128)           // 128
#define SMEM_FLOATS (SM_PZ + 128)
#define SMEM_BYTES  (SMEM_FLOATS * 4)

// ---------------------------------------------------------------------------
// f32x2 helpers
// ---------------------------------------------------------------------------
__device__ __forceinline__ u64 dup2(float a) {
    u64 r; asm("mov.b64 %0, {%1, %1};" : "=l"(r) : "f"(a)); return r;
}
__device__ __forceinline__ u64 pack2(float a, float b) {
    u64 r; asm("mov.b64 %0, {%1, %2};" : "=l"(r) : "f"(a), "f"(b)); return r;
}
__device__ __forceinline__ void unpack2(u64 v, float &a, float &b) {
    asm("mov.b64 {%0, %1}, %2;" : "=f"(a), "=f"(b) : "l"(v));
}
__device__ __forceinline__ void fma2(u64 &d, u64 a, u64 b) {
    asm("fma.rn.f32x2 %0, %1, %2, %0;" : "+l"(d) : "l"(a), "l"(b));
}
__device__ __forceinline__ float sigm(float x) {
    return __fdividef(1.0f, 1.0f + __expf(-x));
}
__device__ __forceinline__ void bar_crew0() {
    asm volatile("bar.sync 1, 128;" ::: "memory");
}

// ---------------------------------------------------------------------------
// 8pt x 4col register-tiled GEMM with A/B (k+1) prefetch — verbatim from the
// 897-us kernel.  pg = tid>>4, cg = tid&15.  acc[p2*4+c].
// Prefetch reads one row past K (valid adjacent smem / weight blob; discarded).
// ---------------------------------------------------------------------------
template <int K, int NC, int UNR>
__device__ __forceinline__ void gemm84(u64* __restrict__ acc,
                                       const float* __restrict__ aT,
                                       const float* __restrict__ B,
                                       int pg, int cg) {
    const float* arow = aT + pg * 8;
    const float* brow = B + cg * 4;
    ulonglong2 a01 = *reinterpret_cast<const ulonglong2*>(arow);
    ulonglong2 a23 = *reinterpret_cast<const ulonglong2*>(arow + 4);
    float4 b4 = *reinterpret_cast<const float4*>(brow);
    #pragma unroll UNR
    for (int k = 0; k < K; k++) {
        const float* an = arow + (k + 1) * ACT_STRIDE;
        ulonglong2 na01 = *reinterpret_cast<const ulonglong2*>(an);
        ulonglong2 na23 = *reinterpret_cast<const ulonglong2*>(an + 4);
        float4 nb4 = *reinterpret_cast<const float4*>(brow + (k + 1) * NC);
        u64 b0 = dup2(b4.x), b1 = dup2(b4.y), b2 = dup2(b4.z), b3 = dup2(b4.w);
        u64 a[4] = {a01.x, a01.y, a23.x, a23.y};
        #pragma unroll
        for (int p = 0; p < 4; p++) {
            fma2(acc[p * 4 + 0], a[p], b0);
            fma2(acc[p * 4 + 1], a[p], b1);
            fma2(acc[p * 4 + 2], a[p], b2);
            fma2(acc[p * 4 + 3], a[p], b3);
        }
        a01 = na01; a23 = na23; b4 = nb4;
    }
}

// ---------------------------------------------------------------------------
// 8pt x 8col variant for the 128-thread crew0 GEMMs (GEMM1/GEMM2).
//   pgA = tid>>3 (0..15), cgA = tid&7 (0..7) -> cols cgA*8..+8
//   acc[p2*8+c]
// ---------------------------------------------------------------------------
template <int K, int NC, int UNR>
__device__ __forceinline__ void gemm88(u64* __restrict__ acc,
                                       const float* __restrict__ aT,
                                       const float* __restrict__ B,
                                       int pgA, int cgA) {
    const float* arow = aT + pgA * 8;
    const float* brow = B + cgA * 8;
    ulonglong2 a01 = *reinterpret_cast<const ulonglong2*>(arow);
    ulonglong2 a23 = *reinterpret_cast<const ulonglong2*>(arow + 4);
    #pragma unroll UNR
    for (int k = 0; k < K; k++) {
        const float* an = arow + (k + 1) * ACT_STRIDE;
        ulonglong2 na01 = *reinterpret_cast<const ulonglong2*>(an);
        ulonglong2 na23 = *reinterpret_cast<const ulonglong2*>(an + 4);
        float4 b0 = *reinterpret_cast<const float4*>(brow + k * NC);
        float4 b1 = *reinterpret_cast<const float4*>(brow + k * NC + 4);
        u64 a[4] = {a01.x, a01.y, a23.x, a23.y};
        float bf[8] = {b0.x, b0.y, b0.z, b0.w, b1.x, b1.y, b1.z, b1.w};
        #pragma unroll
        for (int c = 0; c < 8; c++) {
            u64 bb = dup2(bf[c]);
            fma2(acc[0 * 8 + c], a[0], bb);
            fma2(acc[1 * 8 + c], a[1], bb);
            fma2(acc[2 * 8 + c], a[2], bb);
            fma2(acc[3 * 8 + c], a[3], bb);
        }
        a01 = na01; a23 = na23;
    }
}

// ---------------------------------------------------------------------------
// Prep kernel
// ---------------------------------------------------------------------------
__global__ void prep_weights(const float* __restrict__ W_tiny,
                             const float* __restrict__ b_tiny,
                             const float* __restrict__ Wp1,
                             const float* __restrict__ Wp2,
                             const float* __restrict__ Wp3) {
    int t = threadIdx.x;
    for (int i = t; i < 12 * 64; i += blockDim.x) g_w.wp1[i] = Wp1[i];
    for (int i = t; i < 64 * 64; i += blockDim.x) g_w.wp2[i] = Wp2[i];
    if (t < 64) g_w.wp3[t] = Wp3[t];
    for (int i = t; i < 32 * 68; i += blockDim.x) {
        int k = i / 68, j = i % 68;
        g_w.wt[i] = (j < 65) ? W_tiny[k * 65 + j] : 0.0f;
    }
    if (t < 68) g_w.bt[t] = (t < 65) ? b_tiny[t] : 0.0f;
}

// ---------------------------------------------------------------------------
// Fused kernel: crew0 (0-127) encode->GEMM1->GEMM2->prior  ||  crew1 (128-255)
// hash gather; then joint GEMM3 + assembly + flush (R5 code).
// ---------------------------------------------------------------------------
__global__ void __launch_bounds__(256, 2)
sdf_kernel(const float* __restrict__ inputs,
           const float* __restrict__ tables,
           float* __restrict__ out,
           int N, LevelP P) {
    extern __shared__ float smem[];
    float* sw    = smem;
    float* actT  = smem + TOTW;       // encT / h1T / out-stage
    float* featT = smem + SM_FEAT;
    float* sZ    = smem + SM_Z;
    float* sX64  = smem + SM_X64;
    float* sPZ   = smem + SM_PZ;

    const int tid  = threadIdx.x;
    const int base = blockIdx.x * 128;
    const int cnt  = min(128, N - base);

    // ---- cooperative weight load ----
    {
        const float4* src = reinterpret_cast<const float4*>(g_w.wp1);
        float4* dst = reinterpret_cast<float4*>(sw);
        #pragma unroll
        for (int i = tid; i < TOTW / 4; i += 256) dst[i] = src[i];
    }
    __syncthreads();

    if (tid < 128) {
        // ============================ CREW 0 =================================
        const int pgA = tid >> 3;     // 0..15
        const int cgA = tid & 7;      // 0..7

        // encode own point
        {
            float x = 0.f, y = 0.f, z = 0.f;
            if (tid < cnt) {
                const float* ip = inputs + (size_t)(base + tid) * 3;
                x = ip[0]; y = ip[1]; z = ip[2];
            }
            const float PIF = 3.14159265358979323846f;
            float s, c, e[12];
            sincosf(x * PIF,          &s, &c); e[0] = s; e[3]  = c;
            sincosf(x * (2.0f * PIF), &s, &c); e[1] = s; e[4]  = c;
            sincosf(x * (4.0f * PIF), &s, &c); e[2] = s; e[5]  = c;
            sincosf(y * PIF,          &s, &c); e[6] = s; e[9]  = c;
            sincosf(y * (2.0f * PIF), &s, &c); e[7] = s; e[10] = c;
            sincosf(y * (4.0f * PIF), &s, &c); e[8] = s; e[11] = c;
            #pragma unroll
            for (int i = 0; i < 12; i++)
                actT[i * ACT_STRIDE + tid] = (tid < cnt) ? e[i] : 0.0f;
            sZ[tid] = z;
        }
        bar_crew0();                  // encT complete for all 128 points

        u64 acc8[32];

        // --- GEMM1: h1 = sigmoid(enc @ Wp1) ---
        #pragma unroll
        for (int q = 0; q < 32; q++) acc8[q] = 0ull;
        gemm88<12, 64, 12>(acc8, actT, sw + OFF_WP1, pgA, cgA);
        bar_crew0();                  // encT reads done -> overwrite as h1T
        #pragma unroll
        for (int c = 0; c < 8; c++) {
            float* rw = actT + (cgA * 8 + c) * ACT_STRIDE + pgA * 8;
            #pragma unroll
            for (int p2 = 0; p2 < 4; p2++) {
                float a, b; unpack2(acc8[p2 * 8 + c], a, b);
                *reinterpret_cast<u64*>(rw + 2 * p2) = pack2(sigm(a), sigm(b));
            }
        }
        bar_crew0();                  // h1T visible

        // --- GEMM2: h2 = sigmoid(h1 @ Wp2); prior via warp shuffle ---
        #pragma unroll
        for (int q = 0; q < 32; q++) acc8[q] = 0ull;
        gemm88<64, 64, 8>(acc8, actT, sw + OFF_WP2, pgA, cgA);
        {
            float pp[8];
            #pragma unroll
            for (int i = 0; i < 8; i++) pp[i] = 0.f;
            #pragma unroll
            for (int c = 0; c < 8; c++) {
                const float w3 = sw[OFF_WP3 + cgA * 8 + c];
                #pragma unroll
                for (int p2 = 0; p2 < 4; p2++) {
                    float a, b; unpack2(acc8[p2 * 8 + c], a, b);
                    pp[2 * p2]     += sigm(a) * w3;
                    pp[2 * p2 + 1] += sigm(b) * w3;
                }
            }
            // reduce over the 8 cgA lanes (bits 0-2 of the lane id share pgA)
            #pragma unroll
            for (int m = 1; m < 8; m <<= 1) {
                #pragma unroll
                for (int i = 0; i < 8; i++)
                    pp[i] += __shfl_xor_sync(0xFFFFFFFFu, pp[i], m);
            }
            if (cgA == 0) {
                const float bt0 = sw[OFF_BT];
                #pragma unroll
                for (int i = 0; i < 8; i++) {
                    const int pt = pgA * 8 + i;
                    sPZ[pt] = (sZ[pt] - bt0) - pp[i];     // z - bt0 - prior
                }
            }
        }
    } else {
        // ============================ CREW 1 =================================
        const int p = tid - 128;
        float x = 0.f, y = 0.f;
        if (p < cnt) {
            const float* ip = inputs + (size_t)(base + p) * 3;
            x = ip[0]; y = ip[1];
        }
        float feat[32];
        float x64 = 0.0f;
        if (p < cnt) {
            const float u = __fadd_rn(__fdiv_rn(x, 30.0f), 0.5f);
            const float v = __fadd_rn(__fdiv_rn(y, 30.0f), 0.5f);
            const float2* tb = reinterpret_cast<const float2*>(tables);
            #pragma unroll
            for (int l = 0; l < NLEV; l++) {
                float s  = P.scale[l];
                float px = __fadd_rn(__fmul_rn(u, s), 0.5f);
                float py = __fadd_rn(__fmul_rn(v, s), 0.5f);
                float fx = floorf(px), fy = floorf(py);
                float wx = px - fx,    wy = py - fy;
                int ix = (int)fx, iy = (int)fy;
                int i00, i10, i01, i11;
                if (P.dense[l]) {
                    int r = P.res[l];
                    i00 = ix + iy * r;  i10 = i00 + 1;
                    i01 = i00 + r;      i11 = i01 + 1;
                    i00 = min(max(i00, 0), TSZ - 1);
                    i10 = min(max(i10, 0), TSZ - 1);
                    i01 = min(max(i01, 0), TSZ - 1);
                    i11 = min(max(i11, 0), TSZ - 1);
                } else {
                    unsigned ux = (unsigned)ix, uy = (unsigned)iy;
                    unsigned hy0 = uy * HASH_PRIME;
                    unsigned hy1 = (uy + 1u) * HASH_PRIME;
                    i00 = (int)((ux        ^ hy0) & TMASK);
                    i10 = (int)(((ux + 1u) ^ hy0) & TMASK);
                    i01 = (int)((ux        ^ hy1) & TMASK);
                    i11 = (int)(((ux + 1u) ^ hy1) & TMASK);
                }
                const float2* t = tb + (size_t)l * TSZ;
                float2 f00 = __ldg(t + i00);
                float2 f10 = __ldg(t + i10);
                float2 f01 = __ldg(t + i01);
                float2 f11 = __ldg(t + i11);
                float omx = 1.0f - wx, omy = 1.0f - wy;
                feat[2 * l]     = (f00.x * omx + f10.x * wx) * omy + (f01.x * omx + f11.x * wx) * wy;
                feat[2 * l + 1] = (f00.y * omx + f10.y * wx) * omy + (f01.y * omx + f11.y * wx) * wy;
            }
        } else {
            #pragma unroll
            for (int k = 0; k < 32; k++) feat[k] = 0.0f;
        }
        #pragma unroll
        for (int k = 0; k < 32; k++) {
            featT[k * ACT_STRIDE + p] = feat[k];
            x64 += feat[k] * sw[OFF_WT + k * 68 + 64];
        }
        sX64[p] = x64 + sw[OFF_BT + 64];
    }
    __syncthreads();   // join: featT, sPZ, sX64 all ready; h1T/encT dead

    // =======================================================================
    // GEMM3 (all 256 threads) + assembly + flush — verbatim R5
    // =======================================================================
    const int pg = tid >> 4;
    const int cg = tid & 15;
    u64 acc[16];
    #pragma unroll
    for (int q = 0; q < 16; q++) acc[q] = 0ull;
    gemm84<32, 68, 8>(acc, featT, sw + OFF_WT, pg, cg);

    // assembly into out-stage (actT region; disjoint from featT reads above)
    {
        float* ost = actT;
        #pragma unroll
        for (int c = 0; c < 4; c++) {
            const int col = cg * 4 + c;
            const float bias = sw[OFF_BT + col];
            #pragma unroll
            for (int p2 = 0; p2 < 4; p2++) {
                float a, b; unpack2(acc[p2 * 4 + c], a, b);
                const int pt = pg * 8 + 2 * p2;
                if (col == 0) {
                    ost[pt * 65]       = sPZ[pt] - a;
                    ost[(pt + 1) * 65] = sPZ[pt + 1] - b;
                } else {
                    ost[pt * 65 + col]       = a + bias;
                    ost[(pt + 1) * 65 + col] = b + bias;
                }
            }
        }
        if (tid < 128) ost[tid * 65 + 64] = sX64[tid];
    }
    __syncthreads();

    // coalesced flush
    if (cnt == 128) {
        float4* o4 = reinterpret_cast<float4*>(out + (size_t)base * 65);
        const float4* s4 = reinterpret_cast<const float4*>(actT);
        #pragma unroll
        for (int t = tid; t < (128 * 65) / 4; t += 256) o4[t] = s4[t];
    } else if (cnt > 0) {
        const int tot = cnt * 65;
        for (int t = tid; t < tot; t += 256) out[(size_t)base * 65 + t] = actT[t];
    }
}

// ---------------------------------------------------------------------------
// Launch
// ---------------------------------------------------------------------------
extern "C" void kernel_launch(void* const* d_in, const int* in_sizes, int n_in,
                              void* d_out, int out_size) {
    const float* inputs  = (const float*)d_in[0];
    const float* tables  = (const float*)d_in[1];
    const float* W_tiny  = (const float*)d_in[2];
    const float* b_tiny  = (const float*)d_in[3];
    const float* Wp1     = (const float*)d_in[4];
    const float* Wp2     = (const float*)d_in[5];
    const float* Wp3     = (const float*)d_in[6];
    float* out           = (float*)d_out;

    const int N = in_sizes[0] / 3;

    LevelP P;
    for (int l = 0; l < NLEV; l++) {
        double sc = pow(2.0, (double)l * log2(1.5)) * 16.0 - 1.0;
        int res = (int)ceil(sc) + 1;
        P.scale[l] = (float)sc;
        P.res[l]   = res;
        P.dense[l] = ((long long)res * (long long)res <= (long long)TSZ) ? 1 : 0;
    }

    static int attr_done = 0;
    if (!attr_done) {
        cudaFuncSetAttribute(sdf_kernel,
                             cudaFuncAttributeMaxDynamicSharedMemorySize, SMEM_BYTES);
        attr_done = 1;
    }

    prep_weights<<<1, 256>>>(W_tiny, b_tiny, Wp1, Wp2, Wp3);

    const int tiles = (N + 127) / 128;
    sdf_kernel<<<tiles, 256, SMEM_BYTES>>>(inputs, tables, out, N, P);
}